// round 1
// baseline (speedup 1.0000x reference)
#include <cuda_runtime.h>
#include <cuda_bf16.h>
#include <math.h>

#define DIMC 384
#define HIDC 1536
#define MMAX 16384

// ---------------- scratch (device globals; no allocation allowed) ----------
__device__ float g_y [MMAX * DIMC];        // LN output (reused for both LNs)
__device__ float g_q [MMAX * DIMC];        // q projection
__device__ float g_h [MMAX * HIDC];        // titan MLP hidden
__device__ float g_xn[MMAX * DIMC];        // x + titan branch (residual base)
__device__ float g_hc[MMAX * 3 * HIDC];    // cms hidden concat [M, 4608]
__device__ float g_w2f[HIDC * DIMC];       // titan_w2[4] @ out_w
__device__ float g_b2f[DIMC];
__device__ float g_b2s[DIMC];

// ---------------- helpers ---------------------------------------------------
__device__ __forceinline__ float2 ffma2(float2 a, float2 b, float2 c) {
    float2 d;
    asm("fma.rn.f32x2 %0, %1, %2, %3;"
        : "=l"(reinterpret_cast<unsigned long long&>(d))
        : "l"(reinterpret_cast<unsigned long long&>(a)),
          "l"(reinterpret_cast<unsigned long long&>(b)),
          "l"(reinterpret_cast<unsigned long long&>(c)));
    return d;
}

__device__ __forceinline__ float gelu_exact(float v) {
    return 0.5f * v * (1.0f + erff(v * 0.7071067811865476f));
}

// ---------------- LayerNorm: one warp per row (384 cols) -------------------
__global__ void ln_kernel(const float* __restrict__ x,
                          const float* __restrict__ s,
                          const float* __restrict__ b,
                          float* __restrict__ y, int M) {
    int row = blockIdx.x * 8 + (threadIdx.x >> 5);
    if (row >= M) return;
    int lane = threadIdx.x & 31;
    const float* xr = x + (long)row * DIMC;
    float v[12];
    float sum = 0.f, sq = 0.f;
#pragma unroll
    for (int i = 0; i < 12; i++) {
        v[i] = xr[lane + 32 * i];
        sum += v[i];
        sq  += v[i] * v[i];
    }
#pragma unroll
    for (int o = 16; o; o >>= 1) {
        sum += __shfl_xor_sync(0xffffffffu, sum, o);
        sq  += __shfl_xor_sync(0xffffffffu, sq, o);
    }
    float mean = sum * (1.f / DIMC);
    float var  = sq * (1.f / DIMC) - mean * mean;
    float rstd = rsqrtf(var + 1e-5f);
    float* yr = y + (long)row * DIMC;
#pragma unroll
    for (int i = 0; i < 12; i++) {
        int c = lane + 32 * i;
        yr[c] = (v[i] - mean) * rstd * s[c] + b[c];
    }
}

// ---------------- RoPE-3D in place on q -------------------------------------
// HD=24, RD=8 -> 3 chunks of 4 pairs each, pos from (t,h,w) decomposition.
__global__ void rope_kernel(float* __restrict__ q, int M,
                            const int* __restrict__ pT,
                            const int* __restrict__ pH,
                            const int* __restrict__ pW) {
    int idx = blockIdx.x * blockDim.x + threadIdx.x;
    int total = M * 16 * 12;
    if (idx >= total) return;
    int pr   = idx % 12;
    int head = (idx / 12) & 15;
    int row  = idx / 192;
    int H = *pH, W = *pW, T = *pT;
    int N = T * H * W;
    int n = row % N;
    int c = pr >> 2;   // chunk 0,1,2
    int j = pr & 3;    // pair within chunk
    float pos;
    if (c == 0)      pos = (float)(n / (H * W));
    else if (c == 1) pos = (float)((n % (H * W)) / W);
    else             pos = (float)(n % W);
    // inv_freq = 10000^(-2j/8) = 10^(-j)
    const float tbl[4] = {1.0f, 0.1f, 0.01f, 0.001f};
    float ang = pos * tbl[j];
    float sn, cs;
    sincosf(ang, &sn, &cs);
    long base = (long)row * DIMC + head * 24 + c * 8 + 2 * j;
    float2 p = *(float2*)&q[base];
    float2 o;
    o.x = p.x * cs - p.y * sn;
    o.y = p.x * sn + p.y * cs;
    *(float2*)&q[base] = o;
}

// ---------------- tiny bias-fusion kernels ----------------------------------
__global__ void b2f_kernel(const float* __restrict__ tb2,  // titan_b2[4], 384
                           const float* __restrict__ ow,   // out_w 384x384
                           const float* __restrict__ ob,   // out_b 384
                           float* __restrict__ b2f) {
    int c = blockIdx.x * blockDim.x + threadIdx.x;
    if (c >= DIMC) return;
    float sum = ob[c];
    for (int k = 0; k < DIMC; k++) sum += tb2[k] * ow[k * DIMC + c];
    b2f[c] = sum;
}

__global__ void b2s_kernel(const float* __restrict__ cb2, float* __restrict__ b2s) {
    int c = blockIdx.x * blockDim.x + threadIdx.x;
    if (c >= DIMC) return;
    b2s[c] = cb2[c] + cb2[DIMC + c] + cb2[2 * DIMC + c];
}

// ---------------- SGEMM 128x128x16, 8x8/thread, f32x2 packed FMA ------------
// C[M,N] = A[M,K] @ B[K,N] (+bias) (+res) (gelu). All dims multiples of tile.
// EPI: 0 = (+bias), 1 = gelu(+bias), 2 = (+bias)(+res)
#define BM 128
#define BN 128
#define BK 16

template <int EPI>
__global__ void __launch_bounds__(256, 2)
sgemm_kernel(const float* __restrict__ A, int lda,
             const float* __restrict__ B, int ldb,
             const float* __restrict__ bias,
             const float* __restrict__ res,
             float* __restrict__ C, int ldc, int K) {
    __shared__ float As[BK][BM + 4];   // stride 132 (16B aligned rows)
    __shared__ float Bs[BK][BN];

    const int tid = threadIdx.x;
    const int bm = blockIdx.y * BM;
    const int bn = blockIdx.x * BN;

    const int tx = tid & 15;
    const int ty = tid >> 4;
    const int row0 = ty * 8;
    const int col0 = tx * 8;

    float2 acc[8][4];
#pragma unroll
    for (int i = 0; i < 8; i++)
#pragma unroll
        for (int j = 0; j < 4; j++) acc[i][j] = make_float2(0.f, 0.f);

    const int ak  = tid & 15;   // k within tile
    const int am0 = tid >> 4;   // row stride 16
    const float* Ab = A + (long)bm * lda;
    const float* Bb = B + bn;

    for (int k0 = 0; k0 < K; k0 += BK) {
        // load A tile (transposed into smem)
#pragma unroll
        for (int p = 0; p < 8; p++) {
            int m = am0 + p * 16;
            As[ak][m] = Ab[(long)m * lda + k0 + ak];
        }
        // load B tile (row-major, float4)
#pragma unroll
        for (int p = 0; p < 2; p++) {
            int idx = tid + p * 256;
            int r = idx >> 5;
            int c = (idx & 31) * 4;
            float4 v = *(const float4*)&Bb[(long)(k0 + r) * ldb + c];
            *(float4*)&Bs[r][c] = v;
        }
        __syncthreads();
#pragma unroll
        for (int kk = 0; kk < BK; kk++) {
            float4 a0 = *(const float4*)&As[kk][row0];
            float4 a1 = *(const float4*)&As[kk][row0 + 4];
            float4 b0 = *(const float4*)&Bs[kk][col0];
            float4 b1 = *(const float4*)&Bs[kk][col0 + 4];
            float a[8] = {a0.x, a0.y, a0.z, a0.w, a1.x, a1.y, a1.z, a1.w};
            float2 b[4] = {make_float2(b0.x, b0.y), make_float2(b0.z, b0.w),
                           make_float2(b1.x, b1.y), make_float2(b1.z, b1.w)};
#pragma unroll
            for (int i = 0; i < 8; i++) {
                float2 ai = make_float2(a[i], a[i]);
#pragma unroll
                for (int j = 0; j < 4; j++) acc[i][j] = ffma2(ai, b[j], acc[i][j]);
            }
        }
        __syncthreads();
    }

    // epilogue
    float bb[8];
    if (bias) {
#pragma unroll
        for (int j = 0; j < 8; j++) bb[j] = bias[bn + col0 + j];
    } else {
#pragma unroll
        for (int j = 0; j < 8; j++) bb[j] = 0.f;
    }

#pragma unroll
    for (int i = 0; i < 8; i++) {
        long gm = (long)(bm + row0 + i);
        float v[8];
#pragma unroll
        for (int jj = 0; jj < 4; jj++) {
            v[2 * jj]     = acc[i][jj].x + bb[2 * jj];
            v[2 * jj + 1] = acc[i][jj].y + bb[2 * jj + 1];
        }
        if (EPI == 1) {
#pragma unroll
            for (int j = 0; j < 8; j++) v[j] = gelu_exact(v[j]);
        }
        if (EPI == 2) {
            const float4 r0 = *(const float4*)&res[gm * ldc + bn + col0];
            const float4 r1 = *(const float4*)&res[gm * ldc + bn + col0 + 4];
            v[0] += r0.x; v[1] += r0.y; v[2] += r0.z; v[3] += r0.w;
            v[4] += r1.x; v[5] += r1.y; v[6] += r1.z; v[7] += r1.w;
        }
        *(float4*)&C[gm * ldc + bn + col0]     = make_float4(v[0], v[1], v[2], v[3]);
        *(float4*)&C[gm * ldc + bn + col0 + 4] = make_float4(v[4], v[5], v[6], v[7]);
    }
}

// ---------------- launch ----------------------------------------------------
extern "C" void kernel_launch(void* const* d_in, const int* in_sizes, int n_in,
                              void* d_out, int out_size) {
    const float* x   = (const float*)d_in[0];
    const float* n1s = (const float*)d_in[1];
    const float* n1b = (const float*)d_in[2];
    const float* n2s = (const float*)d_in[3];
    const float* n2b = (const float*)d_in[4];
    const float* q_w = (const float*)d_in[5];
    const float* tw1 = (const float*)d_in[6];
    const float* tb1 = (const float*)d_in[7];
    const float* tw2 = (const float*)d_in[8];
    const float* tb2 = (const float*)d_in[9];
    const float* ow  = (const float*)d_in[10];
    const float* ob  = (const float*)d_in[11];
    const float* cw1 = (const float*)d_in[12];
    const float* cb1 = (const float*)d_in[13];
    const float* cw2 = (const float*)d_in[14];
    const float* cb2 = (const float*)d_in[15];
    const int* dT = (const int*)d_in[16];
    const int* dH = (const int*)d_in[17];
    const int* dW = (const int*)d_in[18];
    float* out = (float*)d_out;

    const int M = in_sizes[0] / DIMC;   // 16384

    float *y, *q, *h, *xn, *hc, *w2f, *b2f, *b2s;
    cudaGetSymbolAddress((void**)&y,   g_y);
    cudaGetSymbolAddress((void**)&q,   g_q);
    cudaGetSymbolAddress((void**)&h,   g_h);
    cudaGetSymbolAddress((void**)&xn,  g_xn);
    cudaGetSymbolAddress((void**)&hc,  g_hc);
    cudaGetSymbolAddress((void**)&w2f, g_w2f);
    cudaGetSymbolAddress((void**)&b2f, g_b2f);
    cudaGetSymbolAddress((void**)&b2s, g_b2s);

    const int MB = M / BM;   // 128

    // (a) precompute fused weight W2f = titan_w2[4] @ out_w  (1536x384x384)
    sgemm_kernel<0><<<dim3(DIMC / BN, HIDC / BM), 256>>>(
        tw2 + 4L * HIDC * DIMC, DIMC, ow, DIMC, nullptr, nullptr, w2f, DIMC, DIMC);
    b2f_kernel<<<(DIMC + 127) / 128, 128>>>(tb2 + 4 * DIMC, ow, ob, b2f);
    b2s_kernel<<<(DIMC + 127) / 128, 128>>>(cb2, b2s);

    // (1) y = LN1(x)
    ln_kernel<<<M / 8, 256>>>(x, n1s, n1b, y, M);

    // (2) q = y @ q_w
    sgemm_kernel<0><<<dim3(DIMC / BN, MB), 256>>>(
        y, DIMC, q_w, DIMC, nullptr, nullptr, q, DIMC, DIMC);

    // (3) rope3d(q) in place
    {
        int total = M * 16 * 12;
        rope_kernel<<<(total + 255) / 256, 256>>>(q, M, dT, dH, dW);
    }

    // (4) h = gelu(q @ titan_w1[4] + titan_b1[4])
    sgemm_kernel<1><<<dim3(HIDC / BN, MB), 256>>>(
        q, DIMC, tw1 + 4L * DIMC * HIDC, HIDC, tb1 + 4 * HIDC, nullptr, h, HIDC, DIMC);

    // (5) xn = x + h @ W2f + b2f
    sgemm_kernel<2><<<dim3(DIMC / BN, MB), 256>>>(
        h, HIDC, w2f, DIMC, b2f, x, xn, DIMC, HIDC);

    // (6) y = LN2(xn)
    ln_kernel<<<M / 8, 256>>>(xn, n2s, n2b, y, M);

    // (7) hc[:, i*1536:(i+1)*1536] = gelu(y @ cms_w1[i] + cms_b1[i])
    for (int i = 0; i < 3; i++) {
        sgemm_kernel<1><<<dim3(HIDC / BN, MB), 256>>>(
            y, DIMC, cw1 + (long)i * DIMC * HIDC, HIDC, cb1 + i * HIDC, nullptr,
            hc + (long)i * HIDC, 3 * HIDC, DIMC);
    }

    // (8) out = xn + hc @ cms_w2(viewed [4608,384]) + b2s
    sgemm_kernel<2><<<dim3(DIMC / BN, MB), 256>>>(
        hc, 3 * HIDC, cw2, DIMC, b2s, xn, out, DIMC, 3 * HIDC);
}

// round 3
// speedup vs baseline: 5.0307x; 5.0307x over previous
#include <cuda_runtime.h>
#include <cuda_bf16.h>
#include <math.h>
#include <stdint.h>

#define DIMC 384
#define HIDC 1536
#define MMAX 16384

// ---------------- scratch (device globals; no allocation allowed) ----------
__device__ __nv_bfloat16 g_y [MMAX * DIMC];          // LN output (bf16)
__device__ float         g_qf[MMAX * DIMC];          // q projection fp32
__device__ __nv_bfloat16 g_qb[MMAX * DIMC];          // q after rope, bf16
__device__ __nv_bfloat16 g_h [MMAX * HIDC];          // titan hidden bf16
__device__ float         g_xn[MMAX * DIMC];          // x + titan branch
__device__ __nv_bfloat16 g_hc[(long)MMAX * 3 * HIDC];// cms hidden concat bf16
__device__ float         g_w2f[HIDC * DIMC];         // titan_w2[4] @ out_w
__device__ __nv_bfloat16 g_qwT [DIMC * DIMC];        // q_w^T
__device__ __nv_bfloat16 g_tw1T[HIDC * DIMC];        // titan_w1[4]^T
__device__ __nv_bfloat16 g_w2fT[DIMC * HIDC];        // w2f^T
__device__ __nv_bfloat16 g_cw1T[3L * HIDC * DIMC];   // cms_w1[i]^T
__device__ __nv_bfloat16 g_cw2T[(long)DIMC * 3 * HIDC]; // cms_w2^T
__device__ float g_b2f[DIMC];
__device__ float g_b2s[DIMC];

// ---------------- helpers ---------------------------------------------------
__device__ __forceinline__ uint32_t smem_u32(const void* p) {
    uint32_t a;
    asm("{ .reg .u64 t; cvta.to.shared.u64 t, %1; cvt.u32.u64 %0, t; }"
        : "=r"(a) : "l"(p));
    return a;
}
__device__ __forceinline__ float gelu_exact(float v) {
    return 0.5f * v * (1.0f + erff(v * 0.7071067811865476f));
}
__device__ __forceinline__ void cp16(uint32_t s, const void* g) {
    asm volatile("cp.async.cg.shared.global [%0], [%1], 16;"
                 :: "r"(s), "l"(g) : "memory");
}
__device__ __forceinline__ void cp_commit() {
    asm volatile("cp.async.commit_group;" ::: "memory");
}
template <int N> __device__ __forceinline__ void cp_wait() {
    asm volatile("cp.async.wait_group %0;" :: "n"(N) : "memory");
}
__device__ __forceinline__ void ldsm4(uint32_t& r0, uint32_t& r1,
                                      uint32_t& r2, uint32_t& r3, uint32_t a) {
    asm volatile("ldmatrix.sync.aligned.m8n8.x4.shared.b16 {%0,%1,%2,%3}, [%4];"
                 : "=r"(r0), "=r"(r1), "=r"(r2), "=r"(r3) : "r"(a));
}
__device__ __forceinline__ void hmma(float* c, const uint32_t* a, const uint32_t* b) {
    asm volatile(
        "mma.sync.aligned.m16n8k16.row.col.f32.bf16.bf16.f32 "
        "{%0,%1,%2,%3}, {%4,%5,%6,%7}, {%8,%9}, {%0,%1,%2,%3};"
        : "+f"(c[0]), "+f"(c[1]), "+f"(c[2]), "+f"(c[3])
        : "r"(a[0]), "r"(a[1]), "r"(a[2]), "r"(a[3]), "r"(b[0]), "r"(b[1]));
}

#define SWZ(off) ((off) ^ (((off) >> 3) & 0x70))

// ---------------- tensor-core GEMM: C[M,N] = A[M,K] @ Bt[N,K]^T -------------
// 128x128 block tile, BK=64 bf16 (128B rows, SW128 swizzle), 3-stage cp.async,
// 8 warps (2x4), warp tile 64x32, mma.sync m16n8k16 bf16.
// EPI: 0 = none, 1 = gelu(+bias), 2 = (+bias)(+res).  OUTBF: 1 = bf16 out.
#define STAGES 3
#define STG_BYTES 32768

template <int EPI, int OUTBF>
__global__ void __launch_bounds__(256, 2)
tgemm(const __nv_bfloat16* __restrict__ A, int lda,
      const __nv_bfloat16* __restrict__ Bt, int ldb,
      const float* __restrict__ bias,
      const float* __restrict__ res, int ldres,
      void* __restrict__ Cout, int ldc, int K) {
    extern __shared__ char dsm[];
    const int tid  = threadIdx.x;
    const int wid  = tid >> 5;
    const int lane = tid & 31;
    const int wm = wid & 1;        // 2 warps along M
    const int wn = wid >> 1;       // 4 warps along N
    const uint32_t sbase = smem_u32(dsm);

    const __nv_bfloat16* Ab = A  + (long)blockIdx.y * 128 * lda;
    const __nv_bfloat16* Bb = Bt + (long)blockIdx.x * 128 * ldb;

    float acc[4][4][4];
#pragma unroll
    for (int i = 0; i < 4; i++)
#pragma unroll
        for (int j = 0; j < 4; j++)
#pragma unroll
            for (int k = 0; k < 4; k++) acc[i][j][k] = 0.f;

    auto load_chunk = [&](int c) {
        uint32_t sb = sbase + (c % STAGES) * STG_BYTES;
        int k0 = c * 64;
#pragma unroll
        for (int p = 0; p < 4; p++) {
            int idx = tid + p * 256;
            int row = idx >> 3, c16 = idx & 7;
            cp16(sb + SWZ(row * 128 + c16 * 16), Ab + (long)row * lda + k0 + c16 * 8);
        }
#pragma unroll
        for (int p = 0; p < 4; p++) {
            int idx = tid + p * 256;
            int row = idx >> 3, c16 = idx & 7;
            cp16(sb + 16384 + SWZ(row * 128 + c16 * 16), Bb + (long)row * ldb + k0 + c16 * 8);
        }
        cp_commit();
    };

    const int nch = K >> 6;
    const int npro = (STAGES - 1 < nch) ? STAGES - 1 : nch;
    for (int c = 0; c < npro; c++) load_chunk(c);

    // precomputed per-lane ldmatrix address offsets (within a stage buffer)
    const int a_row  = wm * 64 + (lane & 7) + (((lane >> 3) & 1) << 3);
    const int a_colb = (lane >> 4) * 16;
    const int b_row  = wn * 32 + (lane & 7) + ((lane >> 4) << 3);
    const int b_colb = ((lane >> 3) & 1) * 16;

    for (int c = 0; c < nch; c++) {
        if (c + STAGES - 1 < nch) {
            load_chunk(c + STAGES - 1);
            cp_wait<STAGES - 2>();
        } else {
            cp_wait<0>();
        }
        __syncthreads();
        uint32_t sA = sbase + (c % STAGES) * STG_BYTES;
        uint32_t sB = sA + 16384;
#pragma unroll
        for (int kk = 0; kk < 4; kk++) {
            uint32_t afr[4][4];
#pragma unroll
            for (int mt = 0; mt < 4; mt++) {
                uint32_t addr = sA + SWZ((a_row + mt * 16) * 128 + kk * 32 + a_colb);
                ldsm4(afr[mt][0], afr[mt][1], afr[mt][2], afr[mt][3], addr);
            }
            uint32_t bfr[4][2];
#pragma unroll
            for (int nb = 0; nb < 2; nb++) {
                uint32_t r0, r1, r2, r3;
                uint32_t addr = sB + SWZ((b_row + nb * 16) * 128 + kk * 32 + b_colb);
                ldsm4(r0, r1, r2, r3, addr);
                bfr[nb * 2][0] = r0; bfr[nb * 2][1] = r1;
                bfr[nb * 2 + 1][0] = r2; bfr[nb * 2 + 1][1] = r3;
            }
#pragma unroll
            for (int mt = 0; mt < 4; mt++)
#pragma unroll
                for (int nt = 0; nt < 4; nt++)
                    hmma(acc[mt][nt], afr[mt], bfr[nt]);
        }
        __syncthreads();
    }

    // ---- epilogue ----
    const int g = lane >> 2, tig = lane & 3;
    const long row0 = (long)blockIdx.y * 128 + wm * 64;
    const int colb  = blockIdx.x * 128 + wn * 32;
    float* Cf = (float*)Cout;
    __nv_bfloat16* Cb = (__nv_bfloat16*)Cout;

#pragma unroll
    for (int mt = 0; mt < 4; mt++) {
#pragma unroll
        for (int h = 0; h < 2; h++) {
            long row = row0 + mt * 16 + g + h * 8;
#pragma unroll
            for (int nt = 0; nt < 4; nt++) {
                int col = colb + nt * 8 + tig * 2;
                float v0 = acc[mt][nt][2 * h];
                float v1 = acc[mt][nt][2 * h + 1];
                if (EPI == 1 || EPI == 2) {
                    v0 += __ldg(bias + col);
                    v1 += __ldg(bias + col + 1);
                }
                if (EPI == 1) { v0 = gelu_exact(v0); v1 = gelu_exact(v1); }
                if (EPI == 2) {
                    float2 r = *(const float2*)(res + row * (long)ldres + col);
                    v0 += r.x; v1 += r.y;
                }
                if (OUTBF) {
                    __nv_bfloat162 t = __floats2bfloat162_rn(v0, v1);
                    *(__nv_bfloat162*)(Cb + row * (long)ldc + col) = t;
                } else {
                    *(float2*)(Cf + row * (long)ldc + col) = make_float2(v0, v1);
                }
            }
        }
    }
}

// ---------------- LayerNorm: one warp per row, bf16 output ------------------
__global__ void ln_kernel(const float* __restrict__ x,
                          const float* __restrict__ s,
                          const float* __restrict__ b,
                          __nv_bfloat16* __restrict__ y, int M) {
    int row = blockIdx.x * 8 + (threadIdx.x >> 5);
    if (row >= M) return;
    int lane = threadIdx.x & 31;
    const float* xr = x + (long)row * DIMC;
    float v[12];
    float sum = 0.f, sq = 0.f;
#pragma unroll
    for (int i = 0; i < 12; i++) {
        v[i] = xr[lane + 32 * i];
        sum += v[i];
        sq  += v[i] * v[i];
    }
#pragma unroll
    for (int o = 16; o; o >>= 1) {
        sum += __shfl_xor_sync(0xffffffffu, sum, o);
        sq  += __shfl_xor_sync(0xffffffffu, sq, o);
    }
    float mean = sum * (1.f / DIMC);
    float var  = sq * (1.f / DIMC) - mean * mean;
    float rstd = rsqrtf(var + 1e-5f);
    __nv_bfloat16* yr = y + (long)row * DIMC;
#pragma unroll
    for (int i = 0; i < 12; i++) {
        int c = lane + 32 * i;
        yr[c] = __float2bfloat16((v[i] - mean) * rstd * s[c] + b[c]);
    }
}

// ---------------- RoPE-3D: q fp32 -> qb bf16 --------------------------------
__global__ void rope_kernel(const float* __restrict__ q,
                            __nv_bfloat16* __restrict__ qb, int M,
                            const int* __restrict__ pT,
                            const int* __restrict__ pH,
                            const int* __restrict__ pW) {
    int idx = blockIdx.x * blockDim.x + threadIdx.x;
    int total = M * 16 * 12;
    if (idx >= total) return;
    int pr   = idx % 12;
    int head = (idx / 12) & 15;
    int row  = idx / 192;
    int H = *pH, W = *pW, T = *pT;
    int N = T * H * W;
    int n = row % N;
    int c = pr >> 2;
    int j = pr & 3;
    float pos;
    if (c == 0)      pos = (float)(n / (H * W));
    else if (c == 1) pos = (float)((n % (H * W)) / W);
    else             pos = (float)(n % W);
    const float tbl[4] = {1.0f, 0.1f, 0.01f, 0.001f};
    float ang = pos * tbl[j];
    float sn, cs;
    sincosf(ang, &sn, &cs);
    long base = (long)row * DIMC + head * 24 + c * 8 + 2 * j;
    float2 p = *(const float2*)&q[base];
    __nv_bfloat162 o = __floats2bfloat162_rn(p.x * cs - p.y * sn, p.x * sn + p.y * cs);
    *(__nv_bfloat162*)&qb[base] = o;
}

// ---------------- transpose+convert: src[R,C] fp32 -> dst[C,R] bf16 ---------
__global__ void transpose_bf16(const float* __restrict__ src,
                               __nv_bfloat16* __restrict__ dst, int R, int C) {
    __shared__ float t[32][33];
    int bx = blockIdx.x * 32, by = blockIdx.y * 32;
#pragma unroll
    for (int i = 0; i < 32; i += 8) {
        int r = by + threadIdx.y + i, c = bx + threadIdx.x;
        if (r < R && c < C) t[threadIdx.y + i][threadIdx.x] = src[(long)r * C + c];
    }
    __syncthreads();
#pragma unroll
    for (int i = 0; i < 32; i += 8) {
        int r = bx + threadIdx.y + i, c = by + threadIdx.x;
        if (r < C && c < R)
            dst[(long)r * R + c] = __float2bfloat16(t[threadIdx.x][threadIdx.y + i]);
    }
}

// ---------------- tiny bias-fusion kernels ----------------------------------
__global__ void b2f_kernel(const float* __restrict__ tb2,
                           const float* __restrict__ ow,
                           const float* __restrict__ ob,
                           float* __restrict__ b2f) {
    int c = blockIdx.x * blockDim.x + threadIdx.x;
    if (c >= DIMC) return;
    float sum = ob[c];
    for (int k = 0; k < DIMC; k++) sum += tb2[k] * ow[k * DIMC + c];
    b2f[c] = sum;
}
__global__ void b2s_kernel(const float* __restrict__ cb2, float* __restrict__ b2s) {
    int c = blockIdx.x * blockDim.x + threadIdx.x;
    if (c >= DIMC) return;
    b2s[c] = cb2[c] + cb2[DIMC + c] + cb2[2 * DIMC + c];
}

// ---------------- fp32 SGEMM (only for w2f precompute, small) ---------------
#define BM 128
#define BN 128
#define BK 16
__device__ __forceinline__ float2 ffma2(float2 a, float2 b, float2 c) {
    float2 d;
    asm("fma.rn.f32x2 %0, %1, %2, %3;"
        : "=l"(reinterpret_cast<unsigned long long&>(d))
        : "l"(reinterpret_cast<unsigned long long&>(a)),
          "l"(reinterpret_cast<unsigned long long&>(b)),
          "l"(reinterpret_cast<unsigned long long&>(c)));
    return d;
}
__global__ void __launch_bounds__(256, 2)
sgemm0(const float* __restrict__ A, int lda,
       const float* __restrict__ B, int ldb,
       float* __restrict__ C, int ldc, int K) {
    __shared__ float As[BK][BM + 4];
    __shared__ float Bs[BK][BN];
    const int tid = threadIdx.x;
    const int bm = blockIdx.y * BM;
    const int bn = blockIdx.x * BN;
    const int tx = tid & 15, ty = tid >> 4;
    const int row0 = ty * 8, col0 = tx * 8;
    float2 acc[8][4];
#pragma unroll
    for (int i = 0; i < 8; i++)
#pragma unroll
        for (int j = 0; j < 4; j++) acc[i][j] = make_float2(0.f, 0.f);
    const int ak = tid & 15, am0 = tid >> 4;
    const float* Ab = A + (long)bm * lda;
    const float* Bb = B + bn;
    for (int k0 = 0; k0 < K; k0 += BK) {
#pragma unroll
        for (int p = 0; p < 8; p++) {
            int m = am0 + p * 16;
            As[ak][m] = Ab[(long)m * lda + k0 + ak];
        }
#pragma unroll
        for (int p = 0; p < 2; p++) {
            int idx = tid + p * 256;
            int r = idx >> 5, c = (idx & 31) * 4;
            *(float4*)&Bs[r][c] = *(const float4*)&Bb[(long)(k0 + r) * ldb + c];
        }
        __syncthreads();
#pragma unroll
        for (int kk = 0; kk < BK; kk++) {
            float4 a0 = *(const float4*)&As[kk][row0];
            float4 a1 = *(const float4*)&As[kk][row0 + 4];
            float4 b0 = *(const float4*)&Bs[kk][col0];
            float4 b1 = *(const float4*)&Bs[kk][col0 + 4];
            float a[8] = {a0.x, a0.y, a0.z, a0.w, a1.x, a1.y, a1.z, a1.w};
            float2 b[4] = {make_float2(b0.x, b0.y), make_float2(b0.z, b0.w),
                           make_float2(b1.x, b1.y), make_float2(b1.z, b1.w)};
#pragma unroll
            for (int i = 0; i < 8; i++) {
                float2 ai = make_float2(a[i], a[i]);
#pragma unroll
                for (int j = 0; j < 4; j++) acc[i][j] = ffma2(ai, b[j], acc[i][j]);
            }
        }
        __syncthreads();
    }
#pragma unroll
    for (int i = 0; i < 8; i++) {
        long gm = (long)(bm + row0 + i);
        *(float4*)&C[gm * ldc + bn + col0] =
            make_float4(acc[i][0].x, acc[i][0].y, acc[i][1].x, acc[i][1].y);
        *(float4*)&C[gm * ldc + bn + col0 + 4] =
            make_float4(acc[i][2].x, acc[i][2].y, acc[i][3].x, acc[i][3].y);
    }
}

// ---------------- launch ----------------------------------------------------
extern "C" void kernel_launch(void* const* d_in, const int* in_sizes, int n_in,
                              void* d_out, int out_size) {
    const float* x   = (const float*)d_in[0];
    const float* n1s = (const float*)d_in[1];
    const float* n1b = (const float*)d_in[2];
    const float* n2s = (const float*)d_in[3];
    const float* n2b = (const float*)d_in[4];
    const float* q_w = (const float*)d_in[5];
    const float* tw1 = (const float*)d_in[6];
    const float* tb1 = (const float*)d_in[7];
    const float* tw2 = (const float*)d_in[8];
    const float* tb2 = (const float*)d_in[9];
    const float* ow  = (const float*)d_in[10];
    const float* ob  = (const float*)d_in[11];
    const float* cw1 = (const float*)d_in[12];
    const float* cb1 = (const float*)d_in[13];
    const float* cw2 = (const float*)d_in[14];
    const float* cb2 = (const float*)d_in[15];
    const int* dT = (const int*)d_in[16];
    const int* dH = (const int*)d_in[17];
    const int* dW = (const int*)d_in[18];
    float* out = (float*)d_out;

    const int M = in_sizes[0] / DIMC;   // 16384
    const int MB = M / 128;

    __nv_bfloat16 *y, *qb, *h, *hc, *qwT, *tw1T, *w2fT, *cw1T, *cw2T;
    float *qf, *xn, *w2f, *b2f, *b2s;
    cudaGetSymbolAddress((void**)&y,    g_y);
    cudaGetSymbolAddress((void**)&qf,   g_qf);
    cudaGetSymbolAddress((void**)&qb,   g_qb);
    cudaGetSymbolAddress((void**)&h,    g_h);
    cudaGetSymbolAddress((void**)&xn,   g_xn);
    cudaGetSymbolAddress((void**)&hc,   g_hc);
    cudaGetSymbolAddress((void**)&w2f,  g_w2f);
    cudaGetSymbolAddress((void**)&qwT,  g_qwT);
    cudaGetSymbolAddress((void**)&tw1T, g_tw1T);
    cudaGetSymbolAddress((void**)&w2fT, g_w2fT);
    cudaGetSymbolAddress((void**)&cw1T, g_cw1T);
    cudaGetSymbolAddress((void**)&cw2T, g_cw2T);
    cudaGetSymbolAddress((void**)&b2f,  g_b2f);
    cudaGetSymbolAddress((void**)&b2s,  g_b2s);

    const int SMEM_SZ = STAGES * STG_BYTES;   // 98304
    cudaFuncSetAttribute(tgemm<0,0>, cudaFuncAttributeMaxDynamicSharedMemorySize, SMEM_SZ);
    cudaFuncSetAttribute(tgemm<1,1>, cudaFuncAttributeMaxDynamicSharedMemorySize, SMEM_SZ);
    cudaFuncSetAttribute(tgemm<2,0>, cudaFuncAttributeMaxDynamicSharedMemorySize, SMEM_SZ);

    dim3 tb(32, 8);

    // ---- weight prep ----
    sgemm0<<<dim3(DIMC / BN, HIDC / BM), 256>>>(
        tw2 + 4L * HIDC * DIMC, DIMC, ow, DIMC, w2f, DIMC, DIMC);
    b2f_kernel<<<3, 128>>>(tb2 + 4 * DIMC, ow, ob, b2f);
    b2s_kernel<<<3, 128>>>(cb2, b2s);
    transpose_bf16<<<dim3(DIMC / 32, DIMC / 32), tb>>>(q_w, qwT, DIMC, DIMC);
    transpose_bf16<<<dim3(HIDC / 32, DIMC / 32), tb>>>(tw1 + 4L * DIMC * HIDC, tw1T, DIMC, HIDC);
    transpose_bf16<<<dim3(DIMC / 32, HIDC / 32), tb>>>(w2f, w2fT, HIDC, DIMC);
    for (int i = 0; i < 3; i++)
        transpose_bf16<<<dim3(HIDC / 32, DIMC / 32), tb>>>(
            cw1 + (long)i * DIMC * HIDC, cw1T + (long)i * HIDC * DIMC, DIMC, HIDC);
    transpose_bf16<<<dim3(DIMC / 32, (3 * HIDC) / 32), tb>>>(cw2, cw2T, 3 * HIDC, DIMC);

    // ---- main pipeline ----
    ln_kernel<<<M / 8, 256>>>(x, n1s, n1b, y, M);

    tgemm<0,0><<<dim3(DIMC / 128, MB), 256, SMEM_SZ>>>(
        y, DIMC, qwT, DIMC, nullptr, nullptr, 0, qf, DIMC, DIMC);

    {
        int total = M * 16 * 12;
        rope_kernel<<<(total + 255) / 256, 256>>>(qf, qb, M, dT, dH, dW);
    }

    tgemm<1,1><<<dim3(HIDC / 128, MB), 256, SMEM_SZ>>>(
        qb, DIMC, tw1T, DIMC, tb1 + 4 * HIDC, nullptr, 0, h, HIDC, DIMC);

    tgemm<2,0><<<dim3(DIMC / 128, MB), 256, SMEM_SZ>>>(
        h, HIDC, w2fT, HIDC, b2f, x, DIMC, xn, DIMC, HIDC);

    ln_kernel<<<M / 8, 256>>>(xn, n2s, n2b, y, M);

    for (int i = 0; i < 3; i++) {
        tgemm<1,1><<<dim3(HIDC / 128, MB), 256, SMEM_SZ>>>(
            y, DIMC, cw1T + (long)i * HIDC * DIMC, DIMC, cb1 + i * HIDC, nullptr, 0,
            hc + (long)i * HIDC, 3 * HIDC, DIMC);
    }

    tgemm<2,0><<<dim3(DIMC / 128, MB), 256, SMEM_SZ>>>(
        hc, 3 * HIDC, cw2T, 3 * HIDC, b2s, xn, DIMC, out, DIMC, 3 * HIDC);
}

// round 4
// speedup vs baseline: 5.5165x; 1.0966x over previous
#include <cuda_runtime.h>
#include <cuda_fp16.h>
#include <math.h>
#include <stdint.h>

#define DIMC 384
#define HIDC 1536
#define MMAX 16384

// ---------------- scratch (device globals; no allocation allowed) ----------
__device__ __half g_y [MMAX * DIMC];            // LN output (fp16)
__device__ __half g_qb[MMAX * DIMC];            // q after rope (fp16)
__device__ __half g_h [MMAX * HIDC];            // titan hidden (fp16)
__device__ float  g_xn[MMAX * DIMC];            // x + titan branch (fp32)
__device__ __half g_hc[(long)MMAX * 3 * HIDC];  // cms hidden concat (fp16)
__device__ float  g_w2f[HIDC * DIMC];           // titan_w2[4] @ out_w (fp32)
__device__ __half g_tw2h[HIDC * DIMC];          // titan_w2[4] as fp16
__device__ __half g_owT [DIMC * DIMC];          // out_w^T fp16
__device__ __half g_qwT [DIMC * DIMC];          // q_w^T
__device__ __half g_tw1T[HIDC * DIMC];          // titan_w1[4]^T
__device__ __half g_w2fT[DIMC * HIDC];          // w2f^T
__device__ __half g_cw1T[3L * HIDC * DIMC];     // cms_w1^T stacked [4608,384]
__device__ __half g_cw2T[(long)DIMC * 3 * HIDC];// cms_w2^T [384,4608]
__device__ float g_b2f[DIMC];
__device__ float g_b2s[DIMC];

// ---------------- helpers ---------------------------------------------------
__device__ __forceinline__ uint32_t smem_u32(const void* p) {
    uint32_t a;
    asm("{ .reg .u64 t; cvta.to.shared.u64 t, %1; cvt.u32.u64 %0, t; }"
        : "=r"(a) : "l"(p));
    return a;
}
__device__ __forceinline__ float gelu_exact(float v) {
    return 0.5f * v * (1.0f + erff(v * 0.7071067811865476f));
}
__device__ __forceinline__ void cp16(uint32_t s, const void* g) {
    asm volatile("cp.async.cg.shared.global [%0], [%1], 16;"
                 :: "r"(s), "l"(g) : "memory");
}
__device__ __forceinline__ void cp_commit() {
    asm volatile("cp.async.commit_group;" ::: "memory");
}
template <int N> __device__ __forceinline__ void cp_wait() {
    asm volatile("cp.async.wait_group %0;" :: "n"(N) : "memory");
}
__device__ __forceinline__ void ldsm4(uint32_t& r0, uint32_t& r1,
                                      uint32_t& r2, uint32_t& r3, uint32_t a) {
    asm volatile("ldmatrix.sync.aligned.m8n8.x4.shared.b16 {%0,%1,%2,%3}, [%4];"
                 : "=r"(r0), "=r"(r1), "=r"(r2), "=r"(r3) : "r"(a));
}
__device__ __forceinline__ void hmma(float* c, const uint32_t* a, const uint32_t* b) {
    asm volatile(
        "mma.sync.aligned.m16n8k16.row.col.f32.f16.f16.f32 "
        "{%0,%1,%2,%3}, {%4,%5,%6,%7}, {%8,%9}, {%0,%1,%2,%3};"
        : "+f"(c[0]), "+f"(c[1]), "+f"(c[2]), "+f"(c[3])
        : "r"(a[0]), "r"(a[1]), "r"(a[2]), "r"(a[3]), "r"(b[0]), "r"(b[1]));
}

#define SWZ(off) ((off) ^ (((off) >> 3) & 0x70))

// ---------------- tensor-core GEMM: C[M,N] = A[M,K] @ Bt[N,K]^T -------------
// 128x128 block tile, BK=64 fp16 (128B rows, SW128 swizzle), 3-stage cp.async,
// 8 warps (2x4), warp tile 64x32, mma.sync m16n8k16 fp16 -> fp32.
// EPI: 0 none, 1 gelu(+bias), 2 (+bias)(+res), 3 rope3d.  OUTH: 1 = fp16 out.
#define STAGES 3
#define STG_BYTES 32768

template <int EPI, int OUTH>
__global__ void __launch_bounds__(256, 2)
tgemm(const __half* __restrict__ A, int lda,
      const __half* __restrict__ Bt, int ldb,
      const float* __restrict__ bias,
      const float* __restrict__ res, int ldres,
      void* __restrict__ Cout, int ldc, int K,
      const int* __restrict__ pT, const int* __restrict__ pH,
      const int* __restrict__ pW) {
    extern __shared__ char dsm[];
    const int tid  = threadIdx.x;
    const int wid  = tid >> 5;
    const int lane = tid & 31;
    const int wm = wid & 1;
    const int wn = wid >> 1;
    const uint32_t sbase = smem_u32(dsm);

    const __half* Ab = A  + (long)blockIdx.y * 128 * lda;
    const __half* Bb = Bt + (long)blockIdx.x * 128 * ldb;

    float acc[4][4][4];
#pragma unroll
    for (int i = 0; i < 4; i++)
#pragma unroll
        for (int j = 0; j < 4; j++)
#pragma unroll
            for (int k = 0; k < 4; k++) acc[i][j][k] = 0.f;

    auto load_chunk = [&](int c) {
        uint32_t sb = sbase + (c % STAGES) * STG_BYTES;
        int k0 = c * 64;
#pragma unroll
        for (int p = 0; p < 4; p++) {
            int idx = tid + p * 256;
            int row = idx >> 3, c16 = idx & 7;
            cp16(sb + SWZ(row * 128 + c16 * 16), Ab + (long)row * lda + k0 + c16 * 8);
        }
#pragma unroll
        for (int p = 0; p < 4; p++) {
            int idx = tid + p * 256;
            int row = idx >> 3, c16 = idx & 7;
            cp16(sb + 16384 + SWZ(row * 128 + c16 * 16), Bb + (long)row * ldb + k0 + c16 * 8);
        }
        cp_commit();
    };

    const int nch = K >> 6;
    const int npro = (STAGES - 1 < nch) ? STAGES - 1 : nch;
    for (int c = 0; c < npro; c++) load_chunk(c);

    const int a_row  = wm * 64 + (lane & 7) + (((lane >> 3) & 1) << 3);
    const int a_colb = (lane >> 4) * 16;
    const int b_row  = wn * 32 + (lane & 7) + ((lane >> 4) << 3);
    const int b_colb = ((lane >> 3) & 1) * 16;

    for (int c = 0; c < nch; c++) {
        if (c + STAGES - 1 < nch) {
            load_chunk(c + STAGES - 1);
            cp_wait<STAGES - 1>();
        } else {
            cp_wait<0>();
        }
        __syncthreads();
        uint32_t sA = sbase + (c % STAGES) * STG_BYTES;
        uint32_t sB = sA + 16384;
#pragma unroll
        for (int kk = 0; kk < 4; kk++) {
            uint32_t afr[4][4];
#pragma unroll
            for (int mt = 0; mt < 4; mt++) {
                uint32_t addr = sA + SWZ((a_row + mt * 16) * 128 + kk * 32 + a_colb);
                ldsm4(afr[mt][0], afr[mt][1], afr[mt][2], afr[mt][3], addr);
            }
            uint32_t bfr[4][2];
#pragma unroll
            for (int nb = 0; nb < 2; nb++) {
                uint32_t r0, r1, r2, r3;
                uint32_t addr = sB + SWZ((b_row + nb * 16) * 128 + kk * 32 + b_colb);
                ldsm4(r0, r1, r2, r3, addr);
                bfr[nb * 2][0] = r0; bfr[nb * 2][1] = r1;
                bfr[nb * 2 + 1][0] = r2; bfr[nb * 2 + 1][1] = r3;
            }
#pragma unroll
            for (int mt = 0; mt < 4; mt++)
#pragma unroll
                for (int nt = 0; nt < 4; nt++)
                    hmma(acc[mt][nt], afr[mt], bfr[nt]);
        }
        __syncthreads();
    }

    // ---- epilogue ----
    const int g = lane >> 2, tig = lane & 3;
    const long row0 = (long)blockIdx.y * 128 + wm * 64;
    const int colb  = blockIdx.x * 128 + wn * 32;
    float* Cf = (float*)Cout;
    __half* Ch = (__half*)Cout;

    int rT = 0, rH = 0, rW = 0;
    if (EPI == 3) { rT = __ldg(pT); rH = __ldg(pH); rW = __ldg(pW); }

#pragma unroll
    for (int mt = 0; mt < 4; mt++) {
#pragma unroll
        for (int h = 0; h < 2; h++) {
            long row = row0 + mt * 16 + g + h * 8;
            float tp = 0.f, hp = 0.f, wp = 0.f;
            if (EPI == 3) {
                int Nn = rT * rH * rW;
                int n = (int)(row % Nn);
                int HW = rH * rW;
                tp = (float)(n / HW);
                int rem = n % HW;
                hp = (float)(rem / rW);
                wp = (float)(rem % rW);
            }
#pragma unroll
            for (int nt = 0; nt < 4; nt++) {
                int col = colb + nt * 8 + tig * 2;
                float v0 = acc[mt][nt][2 * h];
                float v1 = acc[mt][nt][2 * h + 1];
                if (EPI == 1 || EPI == 2) {
                    v0 += __ldg(bias + col);
                    v1 += __ldg(bias + col + 1);
                }
                if (EPI == 1) { v0 = gelu_exact(v0); v1 = gelu_exact(v1); }
                if (EPI == 2) {
                    float2 r = *(const float2*)(res + row * (long)ldres + col);
                    v0 += r.x; v1 += r.y;
                }
                if (EPI == 3) {
                    int hd = col % 24;          // head dim offset (even)
                    int ch = hd >> 3;           // chunk 0/1/2
                    int jj = (hd & 7) >> 1;     // pair index in chunk
                    float pos = (ch == 0) ? tp : ((ch == 1) ? hp : wp);
                    const float tbl[4] = {1.0f, 0.1f, 0.01f, 0.001f};
                    float ang = pos * tbl[jj];
                    float sn, cs;
                    sincosf(ang, &sn, &cs);
                    float n0 = v0 * cs - v1 * sn;
                    float n1 = v0 * sn + v1 * cs;
                    v0 = n0; v1 = n1;
                }
                if (OUTH) {
                    __half2 t = __floats2half2_rn(v0, v1);
                    *(__half2*)(Ch + row * (long)ldc + col) = t;
                } else {
                    *(float2*)(Cf + row * (long)ldc + col) = make_float2(v0, v1);
                }
            }
        }
    }
}

// ---------------- LayerNorm: one warp per row, fp16 output ------------------
__global__ void ln_kernel(const float* __restrict__ x,
                          const float* __restrict__ s,
                          const float* __restrict__ b,
                          __half* __restrict__ y, int M) {
    int row = blockIdx.x * 8 + (threadIdx.x >> 5);
    if (row >= M) return;
    int lane = threadIdx.x & 31;
    const float* xr = x + (long)row * DIMC;
    float v[12];
    float sum = 0.f, sq = 0.f;
#pragma unroll
    for (int i = 0; i < 12; i++) {
        v[i] = xr[lane + 32 * i];
        sum += v[i];
        sq  += v[i] * v[i];
    }
#pragma unroll
    for (int o = 16; o; o >>= 1) {
        sum += __shfl_xor_sync(0xffffffffu, sum, o);
        sq  += __shfl_xor_sync(0xffffffffu, sq, o);
    }
    float mean = sum * (1.f / DIMC);
    float var  = sq * (1.f / DIMC) - mean * mean;
    float rstd = rsqrtf(var + 1e-5f);
    __half* yr = y + (long)row * DIMC;
#pragma unroll
    for (int i = 0; i < 12; i++) {
        int c = lane + 32 * i;
        yr[c] = __float2half((v[i] - mean) * rstd * s[c] + b[c]);
    }
}

// ---------------- transpose+convert: src[R,C] fp32 -> dst[C,R] fp16 ---------
__global__ void transpose_h(const float* __restrict__ src,
                            __half* __restrict__ dst, int R, int C) {
    __shared__ float t[32][33];
    int bx = blockIdx.x * 32, by = blockIdx.y * 32;
#pragma unroll
    for (int i = 0; i < 32; i += 8) {
        int r = by + threadIdx.y + i, c = bx + threadIdx.x;
        if (r < R && c < C) t[threadIdx.y + i][threadIdx.x] = src[(long)r * C + c];
    }
    __syncthreads();
#pragma unroll
    for (int i = 0; i < 32; i += 8) {
        int r = bx + threadIdx.y + i, c = by + threadIdx.x;
        if (r < C && c < R)
            dst[(long)r * R + c] = __float2half(t[threadIdx.x][threadIdx.y + i]);
    }
}

// ---------------- fp32 -> fp16 copy -----------------------------------------
__global__ void conv_h(const float* __restrict__ src, __half* __restrict__ dst,
                       int n) {
    int i = blockIdx.x * blockDim.x + threadIdx.x;
    int idx = i * 4;
    if (idx + 3 < n) {
        float4 v = *(const float4*)(src + idx);
        __half2 a = __floats2half2_rn(v.x, v.y);
        __half2 b = __floats2half2_rn(v.z, v.w);
        *(__half2*)(dst + idx) = a;
        *(__half2*)(dst + idx + 2) = b;
    }
}

// ---------------- tiny bias-fusion kernels ----------------------------------
__global__ void b2f_kernel(const float* __restrict__ tb2,
                           const float* __restrict__ ow,
                           const float* __restrict__ ob,
                           float* __restrict__ b2f) {
    int c = blockIdx.x * blockDim.x + threadIdx.x;
    if (c >= DIMC) return;
    float sum = ob[c];
    for (int k = 0; k < DIMC; k++) sum += tb2[k] * ow[k * DIMC + c];
    b2f[c] = sum;
}
__global__ void b2s_kernel(const float* __restrict__ cb2, float* __restrict__ b2s) {
    int c = blockIdx.x * blockDim.x + threadIdx.x;
    if (c >= DIMC) return;
    b2s[c] = cb2[c] + cb2[DIMC + c] + cb2[2 * DIMC + c];
}

// ---------------- launch ----------------------------------------------------
extern "C" void kernel_launch(void* const* d_in, const int* in_sizes, int n_in,
                              void* d_out, int out_size) {
    const float* x   = (const float*)d_in[0];
    const float* n1s = (const float*)d_in[1];
    const float* n1b = (const float*)d_in[2];
    const float* n2s = (const float*)d_in[3];
    const float* n2b = (const float*)d_in[4];
    const float* q_w = (const float*)d_in[5];
    const float* tw1 = (const float*)d_in[6];
    const float* tb1 = (const float*)d_in[7];
    const float* tw2 = (const float*)d_in[8];
    const float* tb2 = (const float*)d_in[9];
    const float* ow  = (const float*)d_in[10];
    const float* ob  = (const float*)d_in[11];
    const float* cw1 = (const float*)d_in[12];
    const float* cb1 = (const float*)d_in[13];
    const float* cw2 = (const float*)d_in[14];
    const float* cb2 = (const float*)d_in[15];
    const int* dT = (const int*)d_in[16];
    const int* dH = (const int*)d_in[17];
    const int* dW = (const int*)d_in[18];
    float* out = (float*)d_out;

    const int M = in_sizes[0] / DIMC;   // 16384
    const int MB = M / 128;

    __half *y, *qb, *h, *hc, *tw2h, *owT, *qwT, *tw1T, *w2fT, *cw1T, *cw2T;
    float *xn, *w2f, *b2f, *b2s;
    cudaGetSymbolAddress((void**)&y,    g_y);
    cudaGetSymbolAddress((void**)&qb,   g_qb);
    cudaGetSymbolAddress((void**)&h,    g_h);
    cudaGetSymbolAddress((void**)&xn,   g_xn);
    cudaGetSymbolAddress((void**)&hc,   g_hc);
    cudaGetSymbolAddress((void**)&w2f,  g_w2f);
    cudaGetSymbolAddress((void**)&tw2h, g_tw2h);
    cudaGetSymbolAddress((void**)&owT,  g_owT);
    cudaGetSymbolAddress((void**)&qwT,  g_qwT);
    cudaGetSymbolAddress((void**)&tw1T, g_tw1T);
    cudaGetSymbolAddress((void**)&w2fT, g_w2fT);
    cudaGetSymbolAddress((void**)&cw1T, g_cw1T);
    cudaGetSymbolAddress((void**)&cw2T, g_cw2T);
    cudaGetSymbolAddress((void**)&b2f,  g_b2f);
    cudaGetSymbolAddress((void**)&b2s,  g_b2s);

    const int SMEM_SZ = STAGES * STG_BYTES;   // 98304
    cudaFuncSetAttribute(tgemm<0,0>, cudaFuncAttributeMaxDynamicSharedMemorySize, SMEM_SZ);
    cudaFuncSetAttribute(tgemm<1,1>, cudaFuncAttributeMaxDynamicSharedMemorySize, SMEM_SZ);
    cudaFuncSetAttribute(tgemm<2,0>, cudaFuncAttributeMaxDynamicSharedMemorySize, SMEM_SZ);
    cudaFuncSetAttribute(tgemm<3,1>, cudaFuncAttributeMaxDynamicSharedMemorySize, SMEM_SZ);

    dim3 tb(32, 8);

    // ---- weight prep (fp16 path) ----
    conv_h<<<(HIDC * DIMC / 4 + 255) / 256, 256>>>(tw2 + 4L * HIDC * DIMC, tw2h,
                                                   HIDC * DIMC);
    transpose_h<<<dim3(DIMC / 32, DIMC / 32), tb>>>(ow, owT, DIMC, DIMC);
    // w2f = tw2h @ owT^T  (fp32 out)
    tgemm<0,0><<<dim3(DIMC / 128, HIDC / 128), 256, SMEM_SZ>>>(
        tw2h, DIMC, owT, DIMC, nullptr, nullptr, 0, w2f, DIMC, DIMC,
        nullptr, nullptr, nullptr);
    b2f_kernel<<<3, 128>>>(tb2 + 4 * DIMC, ow, ob, b2f);
    b2s_kernel<<<3, 128>>>(cb2, b2s);
    transpose_h<<<dim3(DIMC / 32, DIMC / 32), tb>>>(q_w, qwT, DIMC, DIMC);
    transpose_h<<<dim3(HIDC / 32, DIMC / 32), tb>>>(tw1 + 4L * DIMC * HIDC, tw1T,
                                                    DIMC, HIDC);
    transpose_h<<<dim3(DIMC / 32, HIDC / 32), tb>>>(w2f, w2fT, HIDC, DIMC);
    for (int i = 0; i < 3; i++)
        transpose_h<<<dim3(HIDC / 32, DIMC / 32), tb>>>(
            cw1 + (long)i * DIMC * HIDC, cw1T + (long)i * HIDC * DIMC, DIMC, HIDC);
    transpose_h<<<dim3(DIMC / 32, (3 * HIDC) / 32), tb>>>(cw2, cw2T, 3 * HIDC, DIMC);

    // ---- main pipeline ----
    ln_kernel<<<M / 8, 256>>>(x, n1s, n1b, y, M);

    // q = rope3d(LN1(x) @ q_w)   (rope fused into epilogue)
    tgemm<3,1><<<dim3(DIMC / 128, MB), 256, SMEM_SZ>>>(
        y, DIMC, qwT, DIMC, nullptr, nullptr, 0, qb, DIMC, DIMC, dT, dH, dW);

    // h = gelu(q @ titan_w1[4] + titan_b1[4])
    tgemm<1,1><<<dim3(HIDC / 128, MB), 256, SMEM_SZ>>>(
        qb, DIMC, tw1T, DIMC, tb1 + 4 * HIDC, nullptr, 0, h, HIDC, DIMC,
        nullptr, nullptr, nullptr);

    // xn = x + h @ w2f + b2f
    tgemm<2,0><<<dim3(DIMC / 128, MB), 256, SMEM_SZ>>>(
        h, HIDC, w2fT, HIDC, b2f, x, DIMC, xn, DIMC, HIDC,
        nullptr, nullptr, nullptr);

    ln_kernel<<<M / 8, 256>>>(xn, n2s, n2b, y, M);

    // hc = gelu(y @ [cw1_0|cw1_1|cw1_2] + cb1)   (merged, N=4608)
    tgemm<1,1><<<dim3((3 * HIDC) / 128, MB), 256, SMEM_SZ>>>(
        y, DIMC, cw1T, DIMC, cb1, nullptr, 0, hc, 3 * HIDC, DIMC,
        nullptr, nullptr, nullptr);

    // out = xn + hc @ cw2 + b2s
    tgemm<2,0><<<dim3(DIMC / 128, MB), 256, SMEM_SZ>>>(
        hc, 3 * HIDC, cw2T, 3 * HIDC, b2s, xn, DIMC, out, DIMC, 3 * HIDC,
        nullptr, nullptr, nullptr);
}

// round 5
// speedup vs baseline: 5.7759x; 1.0470x over previous
#include <cuda_runtime.h>
#include <cuda_fp16.h>
#include <math.h>
#include <stdint.h>

#define DIMC 384
#define HIDC 1536
#define MMAX 16384

// ---------------- scratch (device globals; no allocation allowed) ----------
__device__ __half g_y [MMAX * DIMC];            // LN output (fp16)
__device__ __half g_qb[MMAX * DIMC];            // q after rope (fp16)
__device__ __half g_h [MMAX * HIDC];            // titan hidden (fp16)
__device__ float  g_xn[MMAX * DIMC];            // x + titan branch (fp32)
__device__ __half g_hc[(long)MMAX * 3 * HIDC];  // cms hidden concat (fp16)
__device__ __half g_tw2h[HIDC * DIMC];          // titan_w2[4] as fp16
__device__ __half g_owT [DIMC * DIMC];          // out_w^T fp16
__device__ __half g_qwT [DIMC * DIMC];          // q_w^T
__device__ __half g_tw1T[HIDC * DIMC];          // titan_w1[4]^T
__device__ __half g_w2fT[DIMC * HIDC];          // (titan_w2[4] @ out_w)^T fp16
__device__ __half g_cw1T[3L * HIDC * DIMC];     // cms_w1^T stacked [4608,384]
__device__ __half g_cw2T[(long)DIMC * 3 * HIDC];// cms_w2^T [384,4608]
__device__ float g_b2f[DIMC];
__device__ float g_b2s[DIMC];

// ---------------- helpers ---------------------------------------------------
__device__ __forceinline__ uint32_t smem_u32(const void* p) {
    uint32_t a;
    asm("{ .reg .u64 t; cvta.to.shared.u64 t, %1; cvt.u32.u64 %0, t; }"
        : "=r"(a) : "l"(p));
    return a;
}
__device__ __forceinline__ float gelu_exact(float v) {
    return 0.5f * v * (1.0f + erff(v * 0.7071067811865476f));
}
__device__ __forceinline__ void cp16(uint32_t s, const void* g) {
    asm volatile("cp.async.cg.shared.global [%0], [%1], 16;"
                 :: "r"(s), "l"(g) : "memory");
}
__device__ __forceinline__ void cp_commit() {
    asm volatile("cp.async.commit_group;" ::: "memory");
}
template <int N> __device__ __forceinline__ void cp_wait() {
    asm volatile("cp.async.wait_group %0;" :: "n"(N) : "memory");
}
__device__ __forceinline__ void ldsm4(uint32_t& r0, uint32_t& r1,
                                      uint32_t& r2, uint32_t& r3, uint32_t a) {
    asm volatile("ldmatrix.sync.aligned.m8n8.x4.shared.b16 {%0,%1,%2,%3}, [%4];"
                 : "=r"(r0), "=r"(r1), "=r"(r2), "=r"(r3) : "r"(a));
}
__device__ __forceinline__ void hmma(float* c, const uint32_t* a, const uint32_t* b) {
    asm volatile(
        "mma.sync.aligned.m16n8k16.row.col.f32.f16.f16.f32 "
        "{%0,%1,%2,%3}, {%4,%5,%6,%7}, {%8,%9}, {%0,%1,%2,%3};"
        : "+f"(c[0]), "+f"(c[1]), "+f"(c[2]), "+f"(c[3])
        : "r"(a[0]), "r"(a[1]), "r"(a[2]), "r"(a[3]), "r"(b[0]), "r"(b[1]));
}

#define SWZ(off) ((off) ^ (((off) >> 3) & 0x70))

// ---------------- tensor-core GEMM: C[M,N] = A[M,K] @ Bt[N,K]^T -------------
// 128x128 block tile, BK=64 fp16 (128B rows, SW128 swizzle), 3-stage cp.async,
// 8 warps (2x4), warp tile 64x32, mma.sync m16n8k16 fp16 -> fp32.
// EPI: 0 none, 1 gelu(+bias), 2 (+bias)(+res), 3 rope3d.  OUTH: 1 = fp16 out.
#define STAGES 3
#define STG_BYTES 32768

template <int EPI, int OUTH>
__global__ void __launch_bounds__(256, 2)
tgemm(const __half* __restrict__ A, int lda,
      const __half* __restrict__ Bt, int ldb,
      const float* __restrict__ bias,
      const float* __restrict__ res, int ldres,
      void* __restrict__ Cout, int ldc, int K,
      const int* __restrict__ pT, const int* __restrict__ pH,
      const int* __restrict__ pW) {
    extern __shared__ char dsm[];
    const int tid  = threadIdx.x;
    const int wid  = tid >> 5;
    const int lane = tid & 31;
    const int wm = wid & 1;
    const int wn = wid >> 1;
    const uint32_t sbase = smem_u32(dsm);

    const __half* Ab = A  + (long)blockIdx.y * 128 * lda;
    const __half* Bb = Bt + (long)blockIdx.x * 128 * ldb;

    float acc[4][4][4];
#pragma unroll
    for (int i = 0; i < 4; i++)
#pragma unroll
        for (int j = 0; j < 4; j++)
#pragma unroll
            for (int k = 0; k < 4; k++) acc[i][j][k] = 0.f;

    auto load_chunk = [&](int c) {
        uint32_t sb = sbase + (c % STAGES) * STG_BYTES;
        int k0 = c * 64;
#pragma unroll
        for (int p = 0; p < 4; p++) {
            int idx = tid + p * 256;
            int row = idx >> 3, c16 = idx & 7;
            cp16(sb + SWZ(row * 128 + c16 * 16), Ab + (long)row * lda + k0 + c16 * 8);
        }
#pragma unroll
        for (int p = 0; p < 4; p++) {
            int idx = tid + p * 256;
            int row = idx >> 3, c16 = idx & 7;
            cp16(sb + 16384 + SWZ(row * 128 + c16 * 16), Bb + (long)row * ldb + k0 + c16 * 8);
        }
        cp_commit();
    };

    const int nch = K >> 6;
    const int npro = (STAGES - 1 < nch) ? STAGES - 1 : nch;
    for (int c = 0; c < npro; c++) load_chunk(c);

    const int a_row  = wm * 64 + (lane & 7) + (((lane >> 3) & 1) << 3);
    const int a_colb = (lane >> 4) * 16;
    const int b_row  = wn * 32 + (lane & 7) + ((lane >> 4) << 3);
    const int b_colb = ((lane >> 3) & 1) * 16;

    for (int c = 0; c < nch; c++) {
        if (c + STAGES - 1 < nch) {
            load_chunk(c + STAGES - 1);
            cp_wait<STAGES - 1>();
        } else {
            cp_wait<0>();
        }
        __syncthreads();
        uint32_t sA = sbase + (c % STAGES) * STG_BYTES;
        uint32_t sB = sA + 16384;
#pragma unroll
        for (int kk = 0; kk < 4; kk++) {
            uint32_t afr[4][4];
#pragma unroll
            for (int mt = 0; mt < 4; mt++) {
                uint32_t addr = sA + SWZ((a_row + mt * 16) * 128 + kk * 32 + a_colb);
                ldsm4(afr[mt][0], afr[mt][1], afr[mt][2], afr[mt][3], addr);
            }
            uint32_t bfr[4][2];
#pragma unroll
            for (int nb = 0; nb < 2; nb++) {
                uint32_t r0, r1, r2, r3;
                uint32_t addr = sB + SWZ((b_row + nb * 16) * 128 + kk * 32 + b_colb);
                ldsm4(r0, r1, r2, r3, addr);
                bfr[nb * 2][0] = r0; bfr[nb * 2][1] = r1;
                bfr[nb * 2 + 1][0] = r2; bfr[nb * 2 + 1][1] = r3;
            }
#pragma unroll
            for (int mt = 0; mt < 4; mt++)
#pragma unroll
                for (int nt = 0; nt < 4; nt++)
                    hmma(acc[mt][nt], afr[mt], bfr[nt]);
        }
        __syncthreads();
    }

    // ---- epilogue ----
    const int g = lane >> 2, tig = lane & 3;
    const long row0 = (long)blockIdx.y * 128 + wm * 64;
    const int colb  = blockIdx.x * 128 + wn * 32;
    float* Cf = (float*)Cout;
    __half* Ch = (__half*)Cout;

    int rT = 0, rH = 0, rW = 0;
    if (EPI == 3) { rT = __ldg(pT); rH = __ldg(pH); rW = __ldg(pW); }

#pragma unroll
    for (int mt = 0; mt < 4; mt++) {
#pragma unroll
        for (int h = 0; h < 2; h++) {
            long row = row0 + mt * 16 + g + h * 8;
            float tp = 0.f, hp = 0.f, wp = 0.f;
            if (EPI == 3) {
                int Nn = rT * rH * rW;
                int n = (int)(row % Nn);
                int HW = rH * rW;
                tp = (float)(n / HW);
                int rem = n % HW;
                hp = (float)(rem / rW);
                wp = (float)(rem % rW);
            }
#pragma unroll
            for (int nt = 0; nt < 4; nt++) {
                int col = colb + nt * 8 + tig * 2;
                float v0 = acc[mt][nt][2 * h];
                float v1 = acc[mt][nt][2 * h + 1];
                if (EPI == 1 || EPI == 2) {
                    v0 += __ldg(bias + col);
                    v1 += __ldg(bias + col + 1);
                }
                if (EPI == 1) { v0 = gelu_exact(v0); v1 = gelu_exact(v1); }
                if (EPI == 2) {
                    float2 r = *(const float2*)(res + row * (long)ldres + col);
                    v0 += r.x; v1 += r.y;
                }
                if (EPI == 3) {
                    int hd = col % 24;
                    int ch = hd >> 3;
                    int jj = (hd & 7) >> 1;
                    float pos = (ch == 0) ? tp : ((ch == 1) ? hp : wp);
                    const float tbl[4] = {1.0f, 0.1f, 0.01f, 0.001f};
                    float ang = pos * tbl[jj];
                    float sn, cs;
                    sincosf(ang, &sn, &cs);
                    float n0 = v0 * cs - v1 * sn;
                    float n1 = v0 * sn + v1 * cs;
                    v0 = n0; v1 = n1;
                }
                if (OUTH) {
                    __half2 t = __floats2half2_rn(v0, v1);
                    *(__half2*)(Ch + row * (long)ldc + col) = t;
                } else {
                    *(float2*)(Cf + row * (long)ldc + col) = make_float2(v0, v1);
                }
            }
        }
    }
}

// ---------------- LayerNorm: one warp per row, fp16 output ------------------
__global__ void ln_kernel(const float* __restrict__ x,
                          const float* __restrict__ s,
                          const float* __restrict__ b,
                          __half* __restrict__ y, int M) {
    int row = blockIdx.x * 8 + (threadIdx.x >> 5);
    if (row >= M) return;
    int lane = threadIdx.x & 31;
    const float* xr = x + (long)row * DIMC;
    float v[12];
    float sum = 0.f, sq = 0.f;
#pragma unroll
    for (int i = 0; i < 12; i++) {
        v[i] = xr[lane + 32 * i];
        sum += v[i];
        sq  += v[i] * v[i];
    }
#pragma unroll
    for (int o = 16; o; o >>= 1) {
        sum += __shfl_xor_sync(0xffffffffu, sum, o);
        sq  += __shfl_xor_sync(0xffffffffu, sq, o);
    }
    float mean = sum * (1.f / DIMC);
    float var  = sq * (1.f / DIMC) - mean * mean;
    float rstd = rsqrtf(var + 1e-5f);
    __half* yr = y + (long)row * DIMC;
#pragma unroll
    for (int i = 0; i < 12; i++) {
        int c = lane + 32 * i;
        yr[c] = __float2half((v[i] - mean) * rstd * s[c] + b[c]);
    }
}

// ---------------- merged prep: all transposes + convert + b2s ---------------
// 32x32 tile transpose units, block = 256 threads (32x8).
__device__ __forceinline__ void tr_tile(const float* __restrict__ src,
                                        __half* __restrict__ dst,
                                        int R, int C, int txi, int tyi, int tid) {
    __shared__ float t[32][33];
    int tx = tid & 31, ty = tid >> 5;
    int bx = txi * 32, by = tyi * 32;
#pragma unroll
    for (int i = 0; i < 32; i += 8) {
        int r = by + ty + i, c = bx + tx;
        t[ty + i][tx] = src[(long)r * C + c];
    }
    __syncthreads();
#pragma unroll
    for (int i = 0; i < 32; i += 8) {
        int r = bx + ty + i, c = by + tx;
        dst[(long)r * R + c] = __float2half(t[tx][ty + i]);
    }
}

__global__ void prep_all(const float* __restrict__ q_w,
                         const float* __restrict__ ow,
                         const float* __restrict__ tw1,
                         const float* __restrict__ tw2,
                         const float* __restrict__ cw1,
                         const float* __restrict__ cw2,
                         const float* __restrict__ cb2,
                         __half* __restrict__ qwT,
                         __half* __restrict__ owT,
                         __half* __restrict__ tw1T,
                         __half* __restrict__ tw2h,
                         __half* __restrict__ cw1T,
                         __half* __restrict__ cw2T,
                         float* __restrict__ b2s) {
    const int blk = blockIdx.x;
    const int tid = threadIdx.x;
    if (blk < 144) {                         // qwT: 384x384 -> 12x12 tiles
        tr_tile(q_w, qwT, DIMC, DIMC, blk % 12, blk / 12, tid);
    } else if (blk < 288) {                  // owT
        int t = blk - 144;
        tr_tile(ow, owT, DIMC, DIMC, t % 12, t / 12, tid);
    } else if (blk < 864) {                  // tw1T: src 384x1536, 48x12 tiles
        int t = blk - 288;
        tr_tile(tw1 + 4L * DIMC * HIDC, tw1T, DIMC, HIDC, t % 48, t / 48, tid);
    } else if (blk < 2592) {                 // cw1T: 3 slabs of 576 tiles
        int t = blk - 864;
        int slab = t / 576, u = t % 576;
        tr_tile(cw1 + (long)slab * DIMC * HIDC, cw1T + (long)slab * HIDC * DIMC,
                DIMC, HIDC, u % 48, u / 48, tid);
    } else if (blk < 4320) {                 // cw2T: src 4608x384, 12x144 tiles
        int t = blk - 2592;
        tr_tile(cw2, cw2T, 3 * HIDC, DIMC, t % 12, t / 12, tid);
    } else if (blk < 4896) {                 // conv tw2 -> tw2h fp16 (590K elem)
        int t = blk - 4320;
        int idx = (t * 256 + tid) * 4;
        const float* src = tw2 + 4L * HIDC * DIMC;
        float4 v = *(const float4*)(src + idx);
        *(__half2*)(tw2h + idx)     = __floats2half2_rn(v.x, v.y);
        *(__half2*)(tw2h + idx + 2) = __floats2half2_rn(v.z, v.w);
    } else {                                 // b2s: 2 blocks x 256
        int c = (blk - 4896) * 256 + tid;
        if (c < DIMC) b2s[c] = cb2[c] + cb2[DIMC + c] + cb2[2 * DIMC + c];
    }
}

// ---------------- b2f: warp-per-column GEMV ---------------------------------
__global__ void b2f_kernel(const float* __restrict__ tb2,
                           const float* __restrict__ ow,
                           const float* __restrict__ ob,
                           float* __restrict__ b2f) {
    int w = blockIdx.x * 8 + (threadIdx.x >> 5);   // column index / warp
    int lane = threadIdx.x & 31;
    if (w >= DIMC) return;
    float sum = 0.f;
#pragma unroll
    for (int i = 0; i < 12; i++) {
        int k = lane + 32 * i;
        sum += tb2[k] * ow[(long)k * DIMC + w];
    }
#pragma unroll
    for (int o = 16; o; o >>= 1) sum += __shfl_xor_sync(0xffffffffu, sum, o);
    if (lane == 0) b2f[w] = sum + ob[w];
}

// ---------------- launch ----------------------------------------------------
extern "C" void kernel_launch(void* const* d_in, const int* in_sizes, int n_in,
                              void* d_out, int out_size) {
    const float* x   = (const float*)d_in[0];
    const float* n1s = (const float*)d_in[1];
    const float* n1b = (const float*)d_in[2];
    const float* n2s = (const float*)d_in[3];
    const float* n2b = (const float*)d_in[4];
    const float* q_w = (const float*)d_in[5];
    const float* tw1 = (const float*)d_in[6];
    const float* tb1 = (const float*)d_in[7];
    const float* tw2 = (const float*)d_in[8];
    const float* tb2 = (const float*)d_in[9];
    const float* ow  = (const float*)d_in[10];
    const float* ob  = (const float*)d_in[11];
    const float* cw1 = (const float*)d_in[12];
    const float* cb1 = (const float*)d_in[13];
    const float* cw2 = (const float*)d_in[14];
    const float* cb2 = (const float*)d_in[15];
    const int* dT = (const int*)d_in[16];
    const int* dH = (const int*)d_in[17];
    const int* dW = (const int*)d_in[18];
    float* out = (float*)d_out;

    const int M = in_sizes[0] / DIMC;   // 16384
    const int MB = M / 128;

    __half *y, *qb, *h, *hc, *tw2h, *owT, *qwT, *tw1T, *w2fT, *cw1T, *cw2T;
    float *xn, *b2f, *b2s;
    cudaGetSymbolAddress((void**)&y,    g_y);
    cudaGetSymbolAddress((void**)&qb,   g_qb);
    cudaGetSymbolAddress((void**)&h,    g_h);
    cudaGetSymbolAddress((void**)&xn,   g_xn);
    cudaGetSymbolAddress((void**)&hc,   g_hc);
    cudaGetSymbolAddress((void**)&tw2h, g_tw2h);
    cudaGetSymbolAddress((void**)&owT,  g_owT);
    cudaGetSymbolAddress((void**)&qwT,  g_qwT);
    cudaGetSymbolAddress((void**)&tw1T, g_tw1T);
    cudaGetSymbolAddress((void**)&w2fT, g_w2fT);
    cudaGetSymbolAddress((void**)&cw1T, g_cw1T);
    cudaGetSymbolAddress((void**)&cw2T, g_cw2T);
    cudaGetSymbolAddress((void**)&b2f,  g_b2f);
    cudaGetSymbolAddress((void**)&b2s,  g_b2s);

    const int SMEM_SZ = STAGES * STG_BYTES;   // 98304
    cudaFuncSetAttribute(tgemm<0,1>, cudaFuncAttributeMaxDynamicSharedMemorySize, SMEM_SZ);
    cudaFuncSetAttribute(tgemm<1,1>, cudaFuncAttributeMaxDynamicSharedMemorySize, SMEM_SZ);
    cudaFuncSetAttribute(tgemm<2,0>, cudaFuncAttributeMaxDynamicSharedMemorySize, SMEM_SZ);
    cudaFuncSetAttribute(tgemm<3,1>, cudaFuncAttributeMaxDynamicSharedMemorySize, SMEM_SZ);

    // ---- prep: single merged kernel + b2f GEMV + w2fT GEMM ----
    prep_all<<<4898, 256>>>(q_w, ow, tw1, tw2, cw1, cw2, cb2,
                            qwT, owT, tw1T, tw2h, cw1T, cw2T, b2s);
    b2f_kernel<<<48, 256>>>(tb2 + 4 * DIMC, ow, ob, b2f);

    // ln1 has no prep dependency; run before the w2fT GEMM to keep chip busy
    ln_kernel<<<M / 8, 256>>>(x, n1s, n1b, y, M);

    // w2fT[m,n] = sum_k owT[m,k] * tw2h[n,k]  ->  (tw2 @ ow)^T, fp16 direct
    tgemm<0,1><<<dim3(HIDC / 128, DIMC / 128), 256, SMEM_SZ>>>(
        owT, DIMC, tw2h, DIMC, nullptr, nullptr, 0, w2fT, HIDC, DIMC,
        nullptr, nullptr, nullptr);

    // ---- main pipeline ----
    // q = rope3d(LN1(x) @ q_w)   (rope fused into epilogue)
    tgemm<3,1><<<dim3(DIMC / 128, MB), 256, SMEM_SZ>>>(
        y, DIMC, qwT, DIMC, nullptr, nullptr, 0, qb, DIMC, DIMC, dT, dH, dW);

    // h = gelu(q @ titan_w1[4] + titan_b1[4])
    tgemm<1,1><<<dim3(HIDC / 128, MB), 256, SMEM_SZ>>>(
        qb, DIMC, tw1T, DIMC, tb1 + 4 * HIDC, nullptr, 0, h, HIDC, DIMC,
        nullptr, nullptr, nullptr);

    // xn = x + h @ w2f + b2f
    tgemm<2,0><<<dim3(DIMC / 128, MB), 256, SMEM_SZ>>>(
        h, HIDC, w2fT, HIDC, b2f, x, DIMC, xn, DIMC, HIDC,
        nullptr, nullptr, nullptr);

    ln_kernel<<<M / 8, 256>>>(xn, n2s, n2b, y, M);

    // hc = gelu(y @ [cw1_0|cw1_1|cw1_2] + cb1)   (merged, N=4608)
    tgemm<1,1><<<dim3((3 * HIDC) / 128, MB), 256, SMEM_SZ>>>(
        y, DIMC, cw1T, DIMC, cb1, nullptr, 0, hc, 3 * HIDC, DIMC,
        nullptr, nullptr, nullptr);

    // out = xn + hc @ cw2 + b2s
    tgemm<2,0><<<dim3(DIMC / 128, MB), 256, SMEM_SZ>>>(
        hc, 3 * HIDC, cw2T, 3 * HIDC, b2s, xn, DIMC, out, DIMC, 3 * HIDC,
        nullptr, nullptr, nullptr);
}

// round 6
// speedup vs baseline: 6.1056x; 1.0571x over previous
#include <cuda_runtime.h>
#include <cuda_fp16.h>
#include <math.h>
#include <stdint.h>

#define DIMC 384
#define HIDC 1536
#define MMAX 16384

// ---------------- scratch (device globals; no allocation allowed) ----------
__device__ __half g_y [MMAX * DIMC];            // LN output (fp16)
__device__ __half g_qb[MMAX * DIMC];            // q after rope (fp16)
__device__ __half g_h [MMAX * HIDC];            // titan hidden (fp16)
__device__ float  g_xn[MMAX * DIMC];            // x + titan branch (fp32)
__device__ __half g_hc[(long)MMAX * 3 * HIDC];  // cms hidden concat (fp16)
__device__ __half g_tw2h[HIDC * DIMC];          // titan_w2[4] as fp16
__device__ __half g_owT [DIMC * DIMC];          // out_w^T fp16
__device__ __half g_qwT [DIMC * DIMC];          // q_w^T
__device__ __half g_tw1T[HIDC * DIMC];          // titan_w1[4]^T
__device__ __half g_w2fT[DIMC * HIDC];          // (titan_w2[4] @ out_w)^T fp16
__device__ __half g_cw1T[3L * HIDC * DIMC];     // cms_w1^T stacked [4608,384]
__device__ __half g_cw2T[(long)DIMC * 3 * HIDC];// cms_w2^T [384,4608]
__device__ float g_b2f[DIMC];
__device__ float g_b2s[DIMC];

// ---------------- helpers ---------------------------------------------------
__device__ __forceinline__ uint32_t smem_u32(const void* p) {
    uint32_t a;
    asm("{ .reg .u64 t; cvta.to.shared.u64 t, %1; cvt.u32.u64 %0, t; }"
        : "=r"(a) : "l"(p));
    return a;
}
__device__ __forceinline__ float gelu_exact(float v) {
    return 0.5f * v * (1.0f + erff(v * 0.7071067811865476f));
}
__device__ __forceinline__ void cp16(uint32_t s, const void* g) {
    asm volatile("cp.async.cg.shared.global [%0], [%1], 16;"
                 :: "r"(s), "l"(g) : "memory");
}
__device__ __forceinline__ void cp_commit() {
    asm volatile("cp.async.commit_group;" ::: "memory");
}
template <int N> __device__ __forceinline__ void cp_wait() {
    asm volatile("cp.async.wait_group %0;" :: "n"(N) : "memory");
}
__device__ __forceinline__ void ldsm4(uint32_t& r0, uint32_t& r1,
                                      uint32_t& r2, uint32_t& r3, uint32_t a) {
    asm volatile("ldmatrix.sync.aligned.m8n8.x4.shared.b16 {%0,%1,%2,%3}, [%4];"
                 : "=r"(r0), "=r"(r1), "=r"(r2), "=r"(r3) : "r"(a));
}
__device__ __forceinline__ void hmma(float* c, const uint32_t* a, const uint32_t* b) {
    asm volatile(
        "mma.sync.aligned.m16n8k16.row.col.f32.f16.f16.f32 "
        "{%0,%1,%2,%3}, {%4,%5,%6,%7}, {%8,%9}, {%0,%1,%2,%3};"
        : "+f"(c[0]), "+f"(c[1]), "+f"(c[2]), "+f"(c[3])
        : "r"(a[0]), "r"(a[1]), "r"(a[2]), "r"(a[3]), "r"(b[0]), "r"(b[1]));
}

#define SWZ(off) ((off) ^ (((off) >> 3) & 0x70))

// ---------------- tensor-core GEMM: C[M,N] = A[M,K] @ Bt[N,K]^T -------------
// Block tile (64*WM)x128, BK=64 fp16 (128B rows, SW128), 3-stage cp.async,
// 4*WM warps (WMx4), warp tile 64x32, mma.sync m16n8k16 fp16 -> fp32.
// EPI: 0 none, 1 gelu(+bias), 2 (+bias)(+res), 3 rope3d.  OUTH: 1 = fp16 out.
#define STAGES 3

template <int EPI, int OUTH, int WM>
__global__ void __launch_bounds__(WM * 128, 4 - WM)
tgemm(const __half* __restrict__ A, int lda,
      const __half* __restrict__ Bt, int ldb,
      const float* __restrict__ bias,
      const float* __restrict__ res, int ldres,
      void* __restrict__ Cout, int ldc, int K,
      const int* __restrict__ pT, const int* __restrict__ pH,
      const int* __restrict__ pW) {
    constexpr int BMV = 64 * WM;
    constexpr int THREADS = 128 * WM;
    constexpr int STG = (BMV + 128) * 128;      // bytes per stage
    extern __shared__ char dsm[];
    const int tid  = threadIdx.x;
    const int wid  = tid >> 5;
    const int lane = tid & 31;
    const int wm = wid >> 2;       // warps along M
    const int wn = wid & 3;        // warps along N
    const uint32_t sbase = smem_u32(dsm);

    const __half* Ab = A  + (long)blockIdx.y * BMV * lda;
    const __half* Bb = Bt + (long)blockIdx.x * 128 * ldb;

    float acc[4][4][4];
#pragma unroll
    for (int i = 0; i < 4; i++)
#pragma unroll
        for (int j = 0; j < 4; j++)
#pragma unroll
            for (int k = 0; k < 4; k++) acc[i][j][k] = 0.f;

    auto load_chunk = [&](int c) {
        uint32_t sb = sbase + (c % STAGES) * STG;
        int k0 = c * 64;
#pragma unroll
        for (int p = 0; p < 4; p++) {               // A: BMV*8 vec16
            int idx = tid + p * THREADS;
            int row = idx >> 3, c16 = idx & 7;
            cp16(sb + SWZ(row * 128 + c16 * 16), Ab + (long)row * lda + k0 + c16 * 8);
        }
#pragma unroll
        for (int p = 0; p < 8 / WM; p++) {          // B: 1024 vec16
            int idx = tid + p * THREADS;
            int row = idx >> 3, c16 = idx & 7;
            cp16(sb + BMV * 128 + SWZ(row * 128 + c16 * 16),
                 Bb + (long)row * ldb + k0 + c16 * 8);
        }
        cp_commit();
    };

    const int nch = K >> 6;
    const int npro = (STAGES - 1 < nch) ? STAGES - 1 : nch;
    for (int c = 0; c < npro; c++) load_chunk(c);

    const int a_row  = wm * 64 + (lane & 7) + (((lane >> 3) & 1) << 3);
    const int a_colb = (lane >> 4) * 16;
    const int b_row  = wn * 32 + (lane & 7) + ((lane >> 4) << 3);
    const int b_colb = ((lane >> 3) & 1) * 16;

    for (int c = 0; c < nch; c++) {
        if (c + STAGES - 1 < nch) {
            load_chunk(c + STAGES - 1);
            cp_wait<STAGES - 1>();
        } else {
            cp_wait<0>();
        }
        __syncthreads();
        uint32_t sA = sbase + (c % STAGES) * STG;
        uint32_t sB = sA + BMV * 128;
#pragma unroll
        for (int kk = 0; kk < 4; kk++) {
            uint32_t afr[4][4];
#pragma unroll
            for (int mt = 0; mt < 4; mt++) {
                uint32_t addr = sA + SWZ((a_row + mt * 16) * 128 + kk * 32 + a_colb);
                ldsm4(afr[mt][0], afr[mt][1], afr[mt][2], afr[mt][3], addr);
            }
            uint32_t bfr[4][2];
#pragma unroll
            for (int nb = 0; nb < 2; nb++) {
                uint32_t r0, r1, r2, r3;
                uint32_t addr = sB + SWZ((b_row + nb * 16) * 128 + kk * 32 + b_colb);
                ldsm4(r0, r1, r2, r3, addr);
                bfr[nb * 2][0] = r0; bfr[nb * 2][1] = r1;
                bfr[nb * 2 + 1][0] = r2; bfr[nb * 2 + 1][1] = r3;
            }
#pragma unroll
            for (int mt = 0; mt < 4; mt++)
#pragma unroll
                for (int nt = 0; nt < 4; nt++)
                    hmma(acc[mt][nt], afr[mt], bfr[nt]);
        }
        __syncthreads();
    }

    // ---- epilogue ----
    const int g = lane >> 2, tig = lane & 3;
    const long row0 = (long)blockIdx.y * BMV + wm * 64;
    const int colb  = blockIdx.x * 128 + wn * 32;
    float* Cf = (float*)Cout;
    __half* Ch = (__half*)Cout;

    int rT = 0, rH = 0, rW = 0;
    if (EPI == 3) { rT = __ldg(pT); rH = __ldg(pH); rW = __ldg(pW); }

#pragma unroll
    for (int mt = 0; mt < 4; mt++) {
#pragma unroll
        for (int h = 0; h < 2; h++) {
            long row = row0 + mt * 16 + g + h * 8;
            float tp = 0.f, hp = 0.f, wp = 0.f;
            if (EPI == 3) {
                int Nn = rT * rH * rW;
                int n = (int)(row % Nn);
                int HW = rH * rW;
                tp = (float)(n / HW);
                int rem = n % HW;
                hp = (float)(rem / rW);
                wp = (float)(rem % rW);
            }
#pragma unroll
            for (int nt = 0; nt < 4; nt++) {
                int col = colb + nt * 8 + tig * 2;
                float v0 = acc[mt][nt][2 * h];
                float v1 = acc[mt][nt][2 * h + 1];
                if (EPI == 1 || EPI == 2) {
                    v0 += __ldg(bias + col);
                    v1 += __ldg(bias + col + 1);
                }
                if (EPI == 1) { v0 = gelu_exact(v0); v1 = gelu_exact(v1); }
                if (EPI == 2) {
                    float2 r = *(const float2*)(res + row * (long)ldres + col);
                    v0 += r.x; v1 += r.y;
                }
                if (EPI == 3) {
                    int hd = col % 24;
                    int ch = hd >> 3;
                    int jj = (hd & 7) >> 1;
                    float pos = (ch == 0) ? tp : ((ch == 1) ? hp : wp);
                    const float tbl[4] = {1.0f, 0.1f, 0.01f, 0.001f};
                    float ang = pos * tbl[jj];
                    float sn, cs;
                    sincosf(ang, &sn, &cs);
                    float n0 = v0 * cs - v1 * sn;
                    float n1 = v0 * sn + v1 * cs;
                    v0 = n0; v1 = n1;
                }
                if (OUTH) {
                    __half2 t = __floats2half2_rn(v0, v1);
                    *(__half2*)(Ch + row * (long)ldc + col) = t;
                } else {
                    *(float2*)(Cf + row * (long)ldc + col) = make_float2(v0, v1);
                }
            }
        }
    }
}

// ---------------- LayerNorm: one warp per row, fp16 output ------------------
__global__ void ln_kernel(const float* __restrict__ x,
                          const float* __restrict__ s,
                          const float* __restrict__ b,
                          __half* __restrict__ y, int M) {
    int row = blockIdx.x * 8 + (threadIdx.x >> 5);
    if (row >= M) return;
    int lane = threadIdx.x & 31;
    const float* xr = x + (long)row * DIMC;
    int c0 = lane * 2;
    float2 v[6];
    float sum = 0.f, sq = 0.f;
#pragma unroll
    for (int i = 0; i < 6; i++) {
        v[i] = *(const float2*)&xr[c0 + 64 * i];
        sum += v[i].x + v[i].y;
        sq  += v[i].x * v[i].x + v[i].y * v[i].y;
    }
#pragma unroll
    for (int o = 16; o; o >>= 1) {
        sum += __shfl_xor_sync(0xffffffffu, sum, o);
        sq  += __shfl_xor_sync(0xffffffffu, sq, o);
    }
    float mean = sum * (1.f / DIMC);
    float var  = sq * (1.f / DIMC) - mean * mean;
    float rstd = rsqrtf(var + 1e-5f);
    __half* yr = y + (long)row * DIMC;
#pragma unroll
    for (int i = 0; i < 6; i++) {
        int c = c0 + 64 * i;
        float2 sc = *(const float2*)&s[c];
        float2 bc = *(const float2*)&b[c];
        float o0 = (v[i].x - mean) * rstd * sc.x + bc.x;
        float o1 = (v[i].y - mean) * rstd * sc.y + bc.y;
        *(__half2*)&yr[c] = __floats2half2_rn(o0, o1);
    }
}

// ---------------- merged prep: all transposes + convert + b2s ---------------
__device__ __forceinline__ void tr_tile(const float* __restrict__ src,
                                        __half* __restrict__ dst,
                                        int R, int C, int txi, int tyi, int tid) {
    __shared__ float t[32][33];
    int tx = tid & 31, ty = tid >> 5;
    int bx = txi * 32, by = tyi * 32;
#pragma unroll
    for (int i = 0; i < 32; i += 8) {
        int r = by + ty + i, c = bx + tx;
        t[ty + i][tx] = src[(long)r * C + c];
    }
    __syncthreads();
#pragma unroll
    for (int i = 0; i < 32; i += 8) {
        int r = bx + ty + i, c = by + tx;
        dst[(long)r * R + c] = __float2half(t[tx][ty + i]);
    }
}

__global__ void prep_all(const float* __restrict__ q_w,
                         const float* __restrict__ ow,
                         const float* __restrict__ tw1,
                         const float* __restrict__ tw2,
                         const float* __restrict__ cw1,
                         const float* __restrict__ cw2,
                         const float* __restrict__ cb2,
                         __half* __restrict__ qwT,
                         __half* __restrict__ owT,
                         __half* __restrict__ tw1T,
                         __half* __restrict__ tw2h,
                         __half* __restrict__ cw1T,
                         __half* __restrict__ cw2T,
                         float* __restrict__ b2s) {
    const int blk = blockIdx.x;
    const int tid = threadIdx.x;
    if (blk < 144) {
        tr_tile(q_w, qwT, DIMC, DIMC, blk % 12, blk / 12, tid);
    } else if (blk < 288) {
        int t = blk - 144;
        tr_tile(ow, owT, DIMC, DIMC, t % 12, t / 12, tid);
    } else if (blk < 864) {
        int t = blk - 288;
        tr_tile(tw1 + 4L * DIMC * HIDC, tw1T, DIMC, HIDC, t % 48, t / 48, tid);
    } else if (blk < 2592) {
        int t = blk - 864;
        int slab = t / 576, u = t % 576;
        tr_tile(cw1 + (long)slab * DIMC * HIDC, cw1T + (long)slab * HIDC * DIMC,
                DIMC, HIDC, u % 48, u / 48, tid);
    } else if (blk < 4320) {
        int t = blk - 2592;
        tr_tile(cw2, cw2T, 3 * HIDC, DIMC, t % 12, t / 12, tid);
    } else if (blk < 4896) {
        int t = blk - 4320;
        int idx = (t * 256 + tid) * 4;
        const float* src = tw2 + 4L * HIDC * DIMC;
        float4 v = *(const float4*)(src + idx);
        *(__half2*)(tw2h + idx)     = __floats2half2_rn(v.x, v.y);
        *(__half2*)(tw2h + idx + 2) = __floats2half2_rn(v.z, v.w);
    } else {
        int c = (blk - 4896) * 256 + tid;
        if (c < DIMC) b2s[c] = cb2[c] + cb2[DIMC + c] + cb2[2 * DIMC + c];
    }
}

// ---------------- b2f: warp-per-column GEMV ---------------------------------
__global__ void b2f_kernel(const float* __restrict__ tb2,
                           const float* __restrict__ ow,
                           const float* __restrict__ ob,
                           float* __restrict__ b2f) {
    int w = blockIdx.x * 8 + (threadIdx.x >> 5);
    int lane = threadIdx.x & 31;
    if (w >= DIMC) return;
    float sum = 0.f;
#pragma unroll
    for (int i = 0; i < 12; i++) {
        int k = lane + 32 * i;
        sum += tb2[k] * ow[(long)k * DIMC + w];
    }
#pragma unroll
    for (int o = 16; o; o >>= 1) sum += __shfl_xor_sync(0xffffffffu, sum, o);
    if (lane == 0) b2f[w] = sum + ob[w];
}

// ---------------- launch ----------------------------------------------------
extern "C" void kernel_launch(void* const* d_in, const int* in_sizes, int n_in,
                              void* d_out, int out_size) {
    const float* x   = (const float*)d_in[0];
    const float* n1s = (const float*)d_in[1];
    const float* n1b = (const float*)d_in[2];
    const float* n2s = (const float*)d_in[3];
    const float* n2b = (const float*)d_in[4];
    const float* q_w = (const float*)d_in[5];
    const float* tw1 = (const float*)d_in[6];
    const float* tb1 = (const float*)d_in[7];
    const float* tw2 = (const float*)d_in[8];
    const float* tb2 = (const float*)d_in[9];
    const float* ow  = (const float*)d_in[10];
    const float* ob  = (const float*)d_in[11];
    const float* cw1 = (const float*)d_in[12];
    const float* cb1 = (const float*)d_in[13];
    const float* cw2 = (const float*)d_in[14];
    const float* cb2 = (const float*)d_in[15];
    const int* dT = (const int*)d_in[16];
    const int* dH = (const int*)d_in[17];
    const int* dW = (const int*)d_in[18];
    float* out = (float*)d_out;

    const int M = in_sizes[0] / DIMC;   // 16384

    __half *y, *qb, *h, *hc, *tw2h, *owT, *qwT, *tw1T, *w2fT, *cw1T, *cw2T;
    float *xn, *b2f, *b2s;
    cudaGetSymbolAddress((void**)&y,    g_y);
    cudaGetSymbolAddress((void**)&qb,   g_qb);
    cudaGetSymbolAddress((void**)&h,    g_h);
    cudaGetSymbolAddress((void**)&xn,   g_xn);
    cudaGetSymbolAddress((void**)&hc,   g_hc);
    cudaGetSymbolAddress((void**)&tw2h, g_tw2h);
    cudaGetSymbolAddress((void**)&owT,  g_owT);
    cudaGetSymbolAddress((void**)&qwT,  g_qwT);
    cudaGetSymbolAddress((void**)&tw1T, g_tw1T);
    cudaGetSymbolAddress((void**)&w2fT, g_w2fT);
    cudaGetSymbolAddress((void**)&cw1T, g_cw1T);
    cudaGetSymbolAddress((void**)&cw2T, g_cw2T);
    cudaGetSymbolAddress((void**)&b2f,  g_b2f);
    cudaGetSymbolAddress((void**)&b2s,  g_b2s);

    const int SM128 = STAGES * (128 + 128) * 128;   // 98304 (WM=2)
    const int SM64  = STAGES * (64 + 128) * 128;    // 73728 (WM=1)
    cudaFuncSetAttribute(tgemm<0,1,1>, cudaFuncAttributeMaxDynamicSharedMemorySize, SM64);
    cudaFuncSetAttribute(tgemm<3,1,1>, cudaFuncAttributeMaxDynamicSharedMemorySize, SM64);
    cudaFuncSetAttribute(tgemm<2,0,1>, cudaFuncAttributeMaxDynamicSharedMemorySize, SM64);
    cudaFuncSetAttribute(tgemm<1,1,2>, cudaFuncAttributeMaxDynamicSharedMemorySize, SM128);

    // ---- prep: single merged kernel + b2f GEMV + w2fT GEMM ----
    prep_all<<<4898, 256>>>(q_w, ow, tw1, tw2, cw1, cw2, cb2,
                            qwT, owT, tw1T, tw2h, cw1T, cw2T, b2s);
    b2f_kernel<<<48, 256>>>(tb2 + 4 * DIMC, ow, ob, b2f);

    ln_kernel<<<M / 8, 256>>>(x, n1s, n1b, y, M);

    // w2fT = (tw2 @ ow)^T : [384,1536] = owT @ tw2h^T
    tgemm<0,1,1><<<dim3(HIDC / 128, DIMC / 64), 128, SM64>>>(
        owT, DIMC, tw2h, DIMC, nullptr, nullptr, 0, w2fT, HIDC, DIMC,
        nullptr, nullptr, nullptr);

    // q = rope3d(LN1(x) @ q_w)
    tgemm<3,1,1><<<dim3(DIMC / 128, M / 64), 128, SM64>>>(
        y, DIMC, qwT, DIMC, nullptr, nullptr, 0, qb, DIMC, DIMC, dT, dH, dW);

    // h = gelu(q @ titan_w1[4] + titan_b1[4])
    tgemm<1,1,2><<<dim3(HIDC / 128, M / 128), 256, SM128>>>(
        qb, DIMC, tw1T, DIMC, tb1 + 4 * HIDC, nullptr, 0, h, HIDC, DIMC,
        nullptr, nullptr, nullptr);

    // xn = x + h @ w2f + b2f
    tgemm<2,0,1><<<dim3(DIMC / 128, M / 64), 128, SM64>>>(
        h, HIDC, w2fT, HIDC, b2f, x, DIMC, xn, DIMC, HIDC,
        nullptr, nullptr, nullptr);

    ln_kernel<<<M / 8, 256>>>(xn, n2s, n2b, y, M);

    // hc = gelu(y @ [cw1_0|cw1_1|cw1_2] + cb1)
    tgemm<1,1,2><<<dim3((3 * HIDC) / 128, M / 128), 256, SM128>>>(
        y, DIMC, cw1T, DIMC, cb1, nullptr, 0, hc, 3 * HIDC, DIMC,
        nullptr, nullptr, nullptr);

    // out = xn + hc @ cw2 + b2s
    tgemm<2,0,1><<<dim3(DIMC / 128, M / 64), 128, SM64>>>(
        hc, 3 * HIDC, cw2T, 3 * HIDC, b2s, xn, DIMC, out, DIMC, 3 * HIDC,
        nullptr, nullptr, nullptr);
}